// round 5
// baseline (speedup 1.0000x reference)
#include <cuda_runtime.h>
#include <cuda_fp16.h>
#include <cstdint>

// ---------------- problem constants ----------------
#define NROWS 65536
#define DD    512
#define NL    8

// ---------------- tiling ----------------
#define MT      64            // rows per CTA
#define THREADS 256           // 8 warps: 2 (M) x 4 (N); warp tile 32x64
#define NCTAS   (NROWS / MT)  // 1024

#define LDE 264               // halfs, leading dim of e/h tiles (rows conflict-free, 16B aligned)
#define LDO 260               // floats, leading dim of o tile
#define LDB_BYTES 144         // B tile row stride in bytes (64 k-halfs + pad) -> conflict-free ldmatrix

// SMEM layout (bytes)
#define SM_E   0
#define SM_H   (MT * LDE * 2)              // 33792
#define SM_O   (SM_H + MT * LDE * 2)       // 67584
#define SM_B0  (SM_O + MT * LDO * 4)       // 134144
#define SM_B1  (SM_B0 + 256 * LDB_BYTES)   // 171008
#define SM_LJ  (SM_B1 + 256 * LDB_BYTES)   // 207872
#define SM_TOT (SM_LJ + MT * 4 * 4)        // 208896

// packed fp16 weights, W^T layout: [layer][mat(Ws1,Ws2,Wt1,Wt2)][n 256][k 256]
__device__ __half g_wpack2[NL * 4 * 256 * 256];

// ======================= small helpers =======================
__device__ __forceinline__ uint32_t smem_u32(const void* p) {
    uint32_t a;
    asm("{ .reg .u64 t; cvta.to.shared.u64 t, %1; cvt.u32.u64 %0, t; }" : "=r"(a) : "l"(p));
    return a;
}

__device__ __forceinline__ void mma16816(float c[4], const uint32_t a[4], uint32_t b0, uint32_t b1)
{
    asm volatile(
        "mma.sync.aligned.m16n8k16.row.col.f32.f16.f16.f32 "
        "{%0,%1,%2,%3},{%4,%5,%6,%7},{%8,%9},{%0,%1,%2,%3};\n"
        : "+f"(c[0]), "+f"(c[1]), "+f"(c[2]), "+f"(c[3])
        : "r"(a[0]), "r"(a[1]), "r"(a[2]), "r"(a[3]), "r"(b0), "r"(b1));
}

__device__ __forceinline__ void ldm4(uint32_t r[4], uint32_t addr)
{
    asm volatile(
        "ldmatrix.sync.aligned.m8n8.x4.shared.b16 {%0,%1,%2,%3},[%4];\n"
        : "=r"(r[0]), "=r"(r[1]), "=r"(r[2]), "=r"(r[3]) : "r"(addr));
}

__device__ __forceinline__ float tanh_acc(float x)
{
    x = fminf(fmaxf(x, -15.f), 15.f);
    float e2 = __expf(2.f * x);
    return __fdividef(e2 - 1.f, e2 + 1.f);
}

// ======================= weight pack (transpose + fp16) =======================
// g_wpack2[m][n][k] = fp16( W_m[k][n] ), m = layer*4 + {Ws1,Ws2,Wt1,Wt2}
__global__ void pack_w(const float* __restrict__ Ws1, const float* __restrict__ Ws2,
                       const float* __restrict__ Wt1, const float* __restrict__ Wt2)
{
    __shared__ float t[32][33];
    int m = blockIdx.z;                 // 0..31
    int layer = m >> 2, mat = m & 3;
    const float* W = ((mat == 0) ? Ws1 : (mat == 1) ? Ws2 : (mat == 2) ? Wt1 : Wt2)
                     + (size_t)layer * 65536;          // [k][n] 256x256
    int kb = blockIdx.x * 32, nb = blockIdx.y * 32;
    int tx = threadIdx.x, ty = threadIdx.y;
    #pragma unroll
    for (int j = 0; j < 4; j++)
        t[ty + 8 * j][tx] = W[(kb + ty + 8 * j) * 256 + nb + tx];
    __syncthreads();
    __half* dst = g_wpack2 + (size_t)m * 65536;        // [n][k]
    #pragma unroll
    for (int j = 0; j < 4; j++)
        dst[(nb + ty + 8 * j) * 256 + kb + tx] = __float2half_rn(t[tx][ty + 8 * j]);
}

// ======================= B slice loader =======================
// One K-slice: 256 n-rows x 64 k-halfs (128B payload per row, stride 144B). 1 cp.async group.
__device__ __forceinline__ void load_slice(uint32_t dst, const __half* __restrict__ w,
                                           int slice, int tid)
{
    const char* src = (const char*)(w + (size_t)tid * 256 + slice * 64);
    uint32_t d = dst + (uint32_t)tid * LDB_BYTES;
    #pragma unroll
    for (int c = 0; c < 8; c++)
        asm volatile("cp.async.cg.shared.global [%0], [%1], 16;"
                     :: "r"(d + c * 16), "l"(src + c * 16));
    asm volatile("cp.async.commit_group;" ::: "memory");
}

// ======================= GEMM: acc(32x64/warp) += A(64x256 smem) @ W(256x256) =======================
// Streams 4 K=64 slices through b0/b1; prefetches slices 0,1 of w_next at s=2,3.
// Invariant on entry & exit: exactly 2 cp.async groups pending.
__device__ __forceinline__ void run_gemm(uint32_t aTile, uint32_t aoff, uint32_t bLane,
                                         uint32_t b0base, uint32_t b1base,
                                         const __half* __restrict__ w_cur,
                                         const __half* __restrict__ w_next,
                                         float acc[2][8][4], int tid)
{
    #pragma unroll
    for (int mt = 0; mt < 2; mt++)
        #pragma unroll
        for (int nt = 0; nt < 8; nt++)
            #pragma unroll
            for (int q = 0; q < 4; q++) acc[mt][nt][q] = 0.f;

    #pragma unroll
    for (int s = 0; s < 4; s++) {
        asm volatile("cp.async.wait_group 1;" ::: "memory");
        __syncthreads();
        const uint32_t bb = (s & 1) ? b1base : b0base;
        const uint32_t aS = aTile + aoff + (uint32_t)s * 128;   // +64 k-halfs per slice
        const uint32_t bS = bb + bLane;
        #pragma unroll
        for (int ks = 0; ks < 4; ks++) {
            uint32_t a[2][4];
            ldm4(a[0], aS + ks * 32);
            ldm4(a[1], aS + ks * 32 + 16 * LDE * 2);
            uint32_t b[4][4];
            #pragma unroll
            for (int j = 0; j < 4; j++)
                ldm4(b[j], bS + ks * 32 + j * (16 * LDB_BYTES));
            #pragma unroll
            for (int mt = 0; mt < 2; mt++)
                #pragma unroll
                for (int nt = 0; nt < 8; nt++)
                    mma16816(acc[mt][nt], a[mt], b[nt >> 1][(nt & 1) * 2], b[nt >> 1][(nt & 1) * 2 + 1]);
        }
        __syncthreads();
        if (s < 2) load_slice(bb, w_cur, s + 2, tid);
        else       load_slice(bb, w_next, s - 2, tid);
    }
}

// ======================= main fused kernel =======================
__global__ void __launch_bounds__(THREADS, 1) nvp_main(
    const float* __restrict__ z,
    const float* __restrict__ bs1, const float* __restrict__ bs2,
    const float* __restrict__ bt1, const float* __restrict__ bt2,
    float* __restrict__ out)
{
    extern __shared__ char smraw[];
    __half* e_s  = reinterpret_cast<__half*>(smraw + SM_E);
    __half* h_s  = reinterpret_cast<__half*>(smraw + SM_H);
    float*  o_s  = reinterpret_cast<float*>(smraw + SM_O);
    float*  lj_s = reinterpret_cast<float*>(smraw + SM_LJ);

    const uint32_t smb = smem_u32(smraw);
    const int tid  = threadIdx.x;
    const int row0 = blockIdx.x * MT;

    // ---- initial weight prefetch: layer0 Ws1 slices 0,1 (2 groups pending) ----
    load_slice(smb + SM_B0, g_wpack2, 0, tid);
    load_slice(smb + SM_B1, g_wpack2, 1, tid);

    // ---- load z: even cols -> e (fp16) + identity half of out; odd cols -> o (f32 smem) ----
    for (int idx = tid; idx < MT * 256; idx += THREADS) {
        int r = idx >> 8, c = idx & 255;
        float2 p = reinterpret_cast<const float2*>(z + (size_t)(row0 + r) * DD)[c];
        e_s[r * LDE + c] = __float2half_rn(p.x);
        o_s[r * LDO + c] = p.y;
        out[(size_t)(row0 + r) * DD + c] = p.x;
    }

    const int warp = tid >> 5, lane = tid & 31;
    const int wm = warp & 1, wn = warp >> 1;           // 2 x 4 warp grid, warp tile 32x64
    const int g = lane >> 2, tg = lane & 3;
    // A-operand ldmatrix lane map (m16k16 x4)
    const int matq = lane >> 3, within = lane & 7;
    const int rowoff = ((matq & 1) << 3) + within;
    const int koff   = (matq >> 1) << 3;
    const uint32_t aoff = (uint32_t)((wm * 32 + rowoff) * LDE + koff) * 2;
    // B-operand ldmatrix lane map: x4 = 2 n-tiles x 2 k-halves
    const int rowB = wn * 64 + ((matq >> 1) << 3) + within;
    const uint32_t bLane = (uint32_t)rowB * LDB_BYTES + (uint32_t)(matq & 1) * 16;

    const uint32_t eA = smb + SM_E, hA = smb + SM_H;
    const uint32_t b0 = smb + SM_B0, b1 = smb + SM_B1;

    float acc[2][8][4];
    float es [2][8][4];
    float lj[4] = {0.f, 0.f, 0.f, 0.f};

    for (int layer = 0; layer < NL; layer++) {
        const __half* w = g_wpack2 + (size_t)(layer * 4) * 65536;
        const __half* wnext0 = (layer == NL - 1) ? g_wpack2 : w + 4 * 65536;

        // ---- GEMM1s: acc = e @ Ws1 ; h = fp16(relu(acc + bs1)) ----
        run_gemm(eA, aoff, bLane, b0, b1, w, w + 65536, acc, tid);
        #pragma unroll
        for (int mt = 0; mt < 2; mt++)
            #pragma unroll
            for (int nt = 0; nt < 8; nt++) {
                int col0 = wn * 64 + nt * 8 + tg * 2;
                float2 bb = *reinterpret_cast<const float2*>(bs1 + layer * 256 + col0);
                int r0 = wm * 32 + mt * 16 + g;
                __half2 v0 = __floats2half2_rn(fmaxf(acc[mt][nt][0] + bb.x, 0.f),
                                               fmaxf(acc[mt][nt][1] + bb.y, 0.f));
                __half2 v1 = __floats2half2_rn(fmaxf(acc[mt][nt][2] + bb.x, 0.f),
                                               fmaxf(acc[mt][nt][3] + bb.y, 0.f));
                *reinterpret_cast<__half2*>(h_s + r0 * LDE + col0)       = v0;
                *reinterpret_cast<__half2*>(h_s + (r0 + 8) * LDE + col0) = v1;
            }

        // ---- GEMM2s: acc = h @ Ws2 ; s = tanh(acc + bs2); es = exp(s); lj += s ----
        run_gemm(hA, aoff, bLane, b0, b1, w + 65536, w + 2 * 65536, acc, tid);
        #pragma unroll
        for (int mt = 0; mt < 2; mt++)
            #pragma unroll
            for (int nt = 0; nt < 8; nt++) {
                int col0 = wn * 64 + nt * 8 + tg * 2;
                float2 bb = *reinterpret_cast<const float2*>(bs2 + layer * 256 + col0);
                float s0 = tanh_acc(acc[mt][nt][0] + bb.x);
                float s1 = tanh_acc(acc[mt][nt][1] + bb.y);
                float s2 = tanh_acc(acc[mt][nt][2] + bb.x);
                float s3 = tanh_acc(acc[mt][nt][3] + bb.y);
                lj[mt * 2]     += s0 + s1;
                lj[mt * 2 + 1] += s2 + s3;
                es[mt][nt][0] = __expf(s0);
                es[mt][nt][1] = __expf(s1);
                es[mt][nt][2] = __expf(s2);
                es[mt][nt][3] = __expf(s3);
            }

        // ---- GEMM1t: acc = e @ Wt1 ; h = fp16(relu(acc + bt1)) ----
        run_gemm(eA, aoff, bLane, b0, b1, w + 2 * 65536, w + 3 * 65536, acc, tid);
        #pragma unroll
        for (int mt = 0; mt < 2; mt++)
            #pragma unroll
            for (int nt = 0; nt < 8; nt++) {
                int col0 = wn * 64 + nt * 8 + tg * 2;
                float2 bb = *reinterpret_cast<const float2*>(bt1 + layer * 256 + col0);
                int r0 = wm * 32 + mt * 16 + g;
                __half2 v0 = __floats2half2_rn(fmaxf(acc[mt][nt][0] + bb.x, 0.f),
                                               fmaxf(acc[mt][nt][1] + bb.y, 0.f));
                __half2 v1 = __floats2half2_rn(fmaxf(acc[mt][nt][2] + bb.x, 0.f),
                                               fmaxf(acc[mt][nt][3] + bb.y, 0.f));
                *reinterpret_cast<__half2*>(h_s + r0 * LDE + col0)       = v0;
                *reinterpret_cast<__half2*>(h_s + (r0 + 8) * LDE + col0) = v1;
            }

        // ---- GEMM2t: acc = h @ Wt2 ; o = es * o + acc + bt2 ----
        run_gemm(hA, aoff, bLane, b0, b1, w + 3 * 65536, wnext0, acc, tid);
        #pragma unroll
        for (int mt = 0; mt < 2; mt++)
            #pragma unroll
            for (int nt = 0; nt < 8; nt++) {
                int col0 = wn * 64 + nt * 8 + tg * 2;
                float2 bb = *reinterpret_cast<const float2*>(bt2 + layer * 256 + col0);
                int r0 = wm * 32 + mt * 16 + g;
                float2 oa = *reinterpret_cast<float2*>(o_s + r0 * LDO + col0);
                float2 ob = *reinterpret_cast<float2*>(o_s + (r0 + 8) * LDO + col0);
                oa.x = es[mt][nt][0] * oa.x + acc[mt][nt][0] + bb.x;
                oa.y = es[mt][nt][1] * oa.y + acc[mt][nt][1] + bb.y;
                ob.x = es[mt][nt][2] * ob.x + acc[mt][nt][2] + bb.x;
                ob.y = es[mt][nt][3] * ob.y + acc[mt][nt][3] + bb.y;
                *reinterpret_cast<float2*>(o_s + r0 * LDO + col0)       = oa;
                *reinterpret_cast<float2*>(o_s + (r0 + 8) * LDO + col0) = ob;
            }
        // o_s/es positions are thread-private; h_s protected by run_gemm's internal syncs
    }
    asm volatile("cp.async.wait_group 0;" ::: "memory");
    __syncthreads();

    // ---- odd half of output ----
    for (int idx = tid; idx < MT * 256; idx += THREADS) {
        int r = idx >> 8, c = idx & 255;
        out[(size_t)(row0 + r) * DD + 256 + c] = o_s[r * LDO + c];
    }

    // ---- deterministic logjac reduction ----
    #pragma unroll
    for (int k = 0; k < 4; k++) {
        float v = lj[k];
        v += __shfl_down_sync(0xffffffffu, v, 2);
        v += __shfl_down_sync(0xffffffffu, v, 1);
        if (tg == 0) {
            int r = wm * 32 + (k >> 1) * 16 + (k & 1) * 8 + g;
            lj_s[r * 4 + wn] = v;
        }
    }
    __syncthreads();
    if (tid < MT) {
        float v = 0.f;
        #pragma unroll
        for (int j = 0; j < 4; j++) v += lj_s[tid * 4 + j];
        out[(size_t)NROWS * DD + row0 + tid] = v;
    }
}

extern "C" void kernel_launch(void* const* d_in, const int* in_sizes, int n_in,
                              void* d_out, int out_size)
{
    const float* z   = (const float*)d_in[0];
    const float* Ws1 = (const float*)d_in[1];
    const float* bs1 = (const float*)d_in[2];
    const float* Ws2 = (const float*)d_in[3];
    const float* bs2 = (const float*)d_in[4];
    const float* Wt1 = (const float*)d_in[5];
    const float* bt1 = (const float*)d_in[6];
    const float* Wt2 = (const float*)d_in[7];
    const float* bt2 = (const float*)d_in[8];
    float* out = (float*)d_out;

    static bool attr_set = false;
    if (!attr_set) {
        cudaFuncSetAttribute(nvp_main, cudaFuncAttributeMaxDynamicSharedMemorySize, SM_TOT);
        attr_set = true;
    }

    // 1) transpose + fp16-pack weights into [n][k] (deterministic, every call)
    pack_w<<<dim3(8, 8, 32), dim3(32, 8)>>>(Ws1, Ws2, Wt1, Wt2);

    // 2) fused 8-layer RealNVP (legacy HMMA, smem-staged weights)
    nvp_main<<<NCTAS, THREADS, SM_TOT>>>(z, bs1, bs2, bt1, bt2, out);
}

// round 6
// speedup vs baseline: 1.1190x; 1.1190x over previous
#include <cuda_runtime.h>
#include <cuda_fp16.h>
#include <cstdint>

// ---------------- problem constants ----------------
#define NROWS 65536
#define DD    512
#define NL    8

// ---------------- tiling ----------------
#define MT      64            // rows per CTA
#define THREADS 512           // 16 warps: 2 (M) x 8 (N); warp tile 32x32
#define NCTAS   (NROWS / MT)  // 1024

#define LDE 264               // halfs, leading dim of e/h tiles (16B aligned, conflict-free ldmatrix)
#define LDO 260               // floats, leading dim of o tile
#define LDB_BYTES 144         // B tile row stride (64 k-halfs payload + 16B pad) -> conflict-free

// SMEM layout (bytes)
#define SM_E   0
#define SM_H   (MT * LDE * 2)              // 33792
#define SM_O   (SM_H + MT * LDE * 2)       // 67584
#define SM_B0  (SM_O + MT * LDO * 4)       // 134144
#define SM_B1  (SM_B0 + 256 * LDB_BYTES)   // 171008
#define SM_LJ  (SM_B1 + 256 * LDB_BYTES)   // 207872
#define SM_TOT (SM_LJ + MT * 8 * 4)        // 209920

// packed fp16 weights, W^T layout: [layer][mat(Ws1,Ws2,Wt1,Wt2)][n 256][k 256]
__device__ __half g_wpack2[NL * 4 * 256 * 256];

// ======================= small helpers =======================
__device__ __forceinline__ uint32_t smem_u32(const void* p) {
    uint32_t a;
    asm("{ .reg .u64 t; cvta.to.shared.u64 t, %1; cvt.u32.u64 %0, t; }" : "=r"(a) : "l"(p));
    return a;
}

__device__ __forceinline__ void mma16816(float c[4], const uint32_t a[4], uint32_t b0, uint32_t b1)
{
    asm volatile(
        "mma.sync.aligned.m16n8k16.row.col.f32.f16.f16.f32 "
        "{%0,%1,%2,%3},{%4,%5,%6,%7},{%8,%9},{%0,%1,%2,%3};\n"
        : "+f"(c[0]), "+f"(c[1]), "+f"(c[2]), "+f"(c[3])
        : "r"(a[0]), "r"(a[1]), "r"(a[2]), "r"(a[3]), "r"(b0), "r"(b1));
}

__device__ __forceinline__ void ldm4(uint32_t r[4], uint32_t addr)
{
    asm volatile(
        "ldmatrix.sync.aligned.m8n8.x4.shared.b16 {%0,%1,%2,%3},[%4];\n"
        : "=r"(r[0]), "=r"(r[1]), "=r"(r[2]), "=r"(r[3]) : "r"(addr));
}

__device__ __forceinline__ float tanh_acc(float x)
{
    x = fminf(fmaxf(x, -15.f), 15.f);
    float e2 = __expf(2.f * x);
    return __fdividef(e2 - 1.f, e2 + 1.f);
}

// ======================= weight pack (transpose + fp16) =======================
// g_wpack2[m][n][k] = fp16( W_m[k][n] ), m = layer*4 + {Ws1,Ws2,Wt1,Wt2}
__global__ void pack_w(const float* __restrict__ Ws1, const float* __restrict__ Ws2,
                       const float* __restrict__ Wt1, const float* __restrict__ Wt2)
{
    __shared__ float t[32][33];
    int m = blockIdx.z;                 // 0..31
    int layer = m >> 2, mat = m & 3;
    const float* W = ((mat == 0) ? Ws1 : (mat == 1) ? Ws2 : (mat == 2) ? Wt1 : Wt2)
                     + (size_t)layer * 65536;          // [k][n] 256x256
    int kb = blockIdx.x * 32, nb = blockIdx.y * 32;
    int tx = threadIdx.x, ty = threadIdx.y;
    #pragma unroll
    for (int j = 0; j < 4; j++)
        t[ty + 8 * j][tx] = W[(kb + ty + 8 * j) * 256 + nb + tx];
    __syncthreads();
    __half* dst = g_wpack2 + (size_t)m * 65536;        // [n][k]
    #pragma unroll
    for (int j = 0; j < 4; j++)
        dst[(nb + ty + 8 * j) * 256 + kb + tx] = __float2half_rn(t[tx][ty + 8 * j]);
}

// ======================= B slice loader (512 threads) =======================
// One K-slice: 256 n-rows x 64 k-halfs (128B payload/row, 144B stride). 1 cp.async group.
// Thread t covers row t>>1, 64B half (t&1).
__device__ __forceinline__ void load_slice(uint32_t dst, const __half* __restrict__ w,
                                           int slice, int tid)
{
    int row = tid >> 1, half = tid & 1;
    const char* src = (const char*)(w + (size_t)row * 256 + slice * 64 + half * 32);
    uint32_t d = dst + (uint32_t)row * LDB_BYTES + (uint32_t)half * 64;
    #pragma unroll
    for (int c = 0; c < 4; c++)
        asm volatile("cp.async.cg.shared.global [%0], [%1], 16;"
                     :: "r"(d + c * 16), "l"(src + c * 16));
    asm volatile("cp.async.commit_group;" ::: "memory");
}

// ======================= GEMM: acc(32x32/warp) = A(64x256 smem) @ W(256x256) =======================
// Streams 4 K=64 slices through b0/b1; prefetches slices 0,1 of w_next at s=2,3.
// Invariant on entry & exit: exactly 2 cp.async groups pending.
__device__ __forceinline__ void run_gemm(uint32_t aTile, uint32_t aoff, uint32_t bLane,
                                         uint32_t b0base, uint32_t b1base,
                                         const __half* __restrict__ w_cur,
                                         const __half* __restrict__ w_next,
                                         float acc[2][4][4], int tid)
{
    #pragma unroll
    for (int mt = 0; mt < 2; mt++)
        #pragma unroll
        for (int nt = 0; nt < 4; nt++)
            #pragma unroll
            for (int q = 0; q < 4; q++) acc[mt][nt][q] = 0.f;

    #pragma unroll
    for (int s = 0; s < 4; s++) {
        asm volatile("cp.async.wait_group 1;" ::: "memory");
        __syncthreads();
        const uint32_t bb = (s & 1) ? b1base : b0base;
        const uint32_t aS = aTile + aoff + (uint32_t)s * 128;   // +64 k-halfs per slice
        const uint32_t bS = bb + bLane;
        #pragma unroll
        for (int ks = 0; ks < 4; ks++) {
            uint32_t a[2][4];
            ldm4(a[0], aS + ks * 32);
            ldm4(a[1], aS + ks * 32 + 16 * LDE * 2);
            uint32_t b[2][4];
            #pragma unroll
            for (int j = 0; j < 2; j++)
                ldm4(b[j], bS + ks * 32 + j * (16 * LDB_BYTES));
            #pragma unroll
            for (int mt = 0; mt < 2; mt++)
                #pragma unroll
                for (int nt = 0; nt < 4; nt++)
                    mma16816(acc[mt][nt], a[mt], b[nt >> 1][(nt & 1) * 2], b[nt >> 1][(nt & 1) * 2 + 1]);
        }
        __syncthreads();
        if (s < 2) load_slice(bb, w_cur, s + 2, tid);
        else       load_slice(bb, w_next, s - 2, tid);
    }
}

// ======================= main fused kernel =======================
__global__ void __launch_bounds__(THREADS, 1) nvp_main(
    const float* __restrict__ z,
    const float* __restrict__ bs1, const float* __restrict__ bs2,
    const float* __restrict__ bt1, const float* __restrict__ bt2,
    float* __restrict__ out)
{
    extern __shared__ char smraw[];
    __half* e_s  = reinterpret_cast<__half*>(smraw + SM_E);
    __half* h_s  = reinterpret_cast<__half*>(smraw + SM_H);
    float*  o_s  = reinterpret_cast<float*>(smraw + SM_O);
    float*  lj_s = reinterpret_cast<float*>(smraw + SM_LJ);

    const uint32_t smb = smem_u32(smraw);
    const int tid  = threadIdx.x;
    const int row0 = blockIdx.x * MT;

    // ---- initial weight prefetch: layer0 Ws1 slices 0,1 (2 groups pending) ----
    load_slice(smb + SM_B0, g_wpack2, 0, tid);
    load_slice(smb + SM_B1, g_wpack2, 1, tid);

    // ---- load z: even cols -> e (fp16) + identity half of out; odd cols -> o (f32) ----
    for (int idx = tid; idx < MT * 256; idx += THREADS) {
        int r = idx >> 8, c = idx & 255;
        float2 p = reinterpret_cast<const float2*>(z + (size_t)(row0 + r) * DD)[c];
        e_s[r * LDE + c] = __float2half_rn(p.x);
        o_s[r * LDO + c] = p.y;
        out[(size_t)(row0 + r) * DD + c] = p.x;
    }

    const int warp = tid >> 5, lane = tid & 31;
    const int wm = warp & 1, wn = warp >> 1;           // 2 x 8 warp grid, warp tile 32x32
    const int g = lane >> 2, tg = lane & 3;
    // A-operand ldmatrix lane map (m16k16 x4)
    const int matq = lane >> 3, within = lane & 7;
    const int rowoff = ((matq & 1) << 3) + within;
    const int koff   = (matq >> 1) << 3;
    const uint32_t aoff = (uint32_t)((wm * 32 + rowoff) * LDE + koff) * 2;
    // B-operand ldmatrix lane map: x4 = 2 n-octets x 2 k-halves
    const int rowB = wn * 32 + ((matq >> 1) << 3) + within;
    const uint32_t bLane = (uint32_t)rowB * LDB_BYTES + (uint32_t)(matq & 1) * 16;

    const uint32_t eA = smb + SM_E, hA = smb + SM_H;
    const uint32_t b0 = smb + SM_B0, b1 = smb + SM_B1;

    float acc[2][4][4];
    float es [2][4][4];
    float lj[4] = {0.f, 0.f, 0.f, 0.f};

    for (int layer = 0; layer < NL; layer++) {
        const __half* w = g_wpack2 + (size_t)(layer * 4) * 65536;
        const __half* wnext0 = (layer == NL - 1) ? g_wpack2 : w + 4 * 65536;

        // ---- GEMM1s: acc = e @ Ws1 ; h = fp16(relu(acc + bs1)) ----
        run_gemm(eA, aoff, bLane, b0, b1, w, w + 65536, acc, tid);
        #pragma unroll
        for (int mt = 0; mt < 2; mt++)
            #pragma unroll
            for (int nt = 0; nt < 4; nt++) {
                int col0 = wn * 32 + nt * 8 + tg * 2;
                float2 bb = *reinterpret_cast<const float2*>(bs1 + layer * 256 + col0);
                int r0 = wm * 32 + mt * 16 + g;
                __half2 v0 = __floats2half2_rn(fmaxf(acc[mt][nt][0] + bb.x, 0.f),
                                               fmaxf(acc[mt][nt][1] + bb.y, 0.f));
                __half2 v1 = __floats2half2_rn(fmaxf(acc[mt][nt][2] + bb.x, 0.f),
                                               fmaxf(acc[mt][nt][3] + bb.y, 0.f));
                *reinterpret_cast<__half2*>(h_s + r0 * LDE + col0)       = v0;
                *reinterpret_cast<__half2*>(h_s + (r0 + 8) * LDE + col0) = v1;
            }

        // ---- GEMM2s: acc = h @ Ws2 ; s = tanh(acc + bs2); es = exp(s); lj += s ----
        run_gemm(hA, aoff, bLane, b0, b1, w + 65536, w + 2 * 65536, acc, tid);
        #pragma unroll
        for (int mt = 0; mt < 2; mt++)
            #pragma unroll
            for (int nt = 0; nt < 4; nt++) {
                int col0 = wn * 32 + nt * 8 + tg * 2;
                float2 bb = *reinterpret_cast<const float2*>(bs2 + layer * 256 + col0);
                float s0 = tanh_acc(acc[mt][nt][0] + bb.x);
                float s1 = tanh_acc(acc[mt][nt][1] + bb.y);
                float s2 = tanh_acc(acc[mt][nt][2] + bb.x);
                float s3 = tanh_acc(acc[mt][nt][3] + bb.y);
                lj[mt * 2]     += s0 + s1;
                lj[mt * 2 + 1] += s2 + s3;
                es[mt][nt][0] = __expf(s0);
                es[mt][nt][1] = __expf(s1);
                es[mt][nt][2] = __expf(s2);
                es[mt][nt][3] = __expf(s3);
            }

        // ---- GEMM1t: acc = e @ Wt1 ; h = fp16(relu(acc + bt1)) ----
        run_gemm(eA, aoff, bLane, b0, b1, w + 2 * 65536, w + 3 * 65536, acc, tid);
        #pragma unroll
        for (int mt = 0; mt < 2; mt++)
            #pragma unroll
            for (int nt = 0; nt < 4; nt++) {
                int col0 = wn * 32 + nt * 8 + tg * 2;
                float2 bb = *reinterpret_cast<const float2*>(bt1 + layer * 256 + col0);
                int r0 = wm * 32 + mt * 16 + g;
                __half2 v0 = __floats2half2_rn(fmaxf(acc[mt][nt][0] + bb.x, 0.f),
                                               fmaxf(acc[mt][nt][1] + bb.y, 0.f));
                __half2 v1 = __floats2half2_rn(fmaxf(acc[mt][nt][2] + bb.x, 0.f),
                                               fmaxf(acc[mt][nt][3] + bb.y, 0.f));
                *reinterpret_cast<__half2*>(h_s + r0 * LDE + col0)       = v0;
                *reinterpret_cast<__half2*>(h_s + (r0 + 8) * LDE + col0) = v1;
            }

        // ---- GEMM2t: acc = h @ Wt2 ; o = es * o + acc + bt2 ----
        run_gemm(hA, aoff, bLane, b0, b1, w + 3 * 65536, wnext0, acc, tid);
        #pragma unroll
        for (int mt = 0; mt < 2; mt++)
            #pragma unroll
            for (int nt = 0; nt < 4; nt++) {
                int col0 = wn * 32 + nt * 8 + tg * 2;
                float2 bb = *reinterpret_cast<const float2*>(bt2 + layer * 256 + col0);
                int r0 = wm * 32 + mt * 16 + g;
                float2 oa = *reinterpret_cast<float2*>(o_s + r0 * LDO + col0);
                float2 ob = *reinterpret_cast<float2*>(o_s + (r0 + 8) * LDO + col0);
                oa.x = es[mt][nt][0] * oa.x + acc[mt][nt][0] + bb.x;
                oa.y = es[mt][nt][1] * oa.y + acc[mt][nt][1] + bb.y;
                ob.x = es[mt][nt][2] * ob.x + acc[mt][nt][2] + bb.x;
                ob.y = es[mt][nt][3] * ob.y + acc[mt][nt][3] + bb.y;
                *reinterpret_cast<float2*>(o_s + r0 * LDO + col0)       = oa;
                *reinterpret_cast<float2*>(o_s + (r0 + 8) * LDO + col0) = ob;
            }
        // o_s/es positions are thread-private; h_s protected by run_gemm's internal syncs
    }
    asm volatile("cp.async.wait_group 0;" ::: "memory");
    __syncthreads();

    // ---- odd half of output ----
    for (int idx = tid; idx < MT * 256; idx += THREADS) {
        int r = idx >> 8, c = idx & 255;
        out[(size_t)(row0 + r) * DD + 256 + c] = o_s[r * LDO + c];
    }

    // ---- deterministic logjac reduction ----
    #pragma unroll
    for (int k = 0; k < 4; k++) {
        float v = lj[k];
        v += __shfl_down_sync(0xffffffffu, v, 2);
        v += __shfl_down_sync(0xffffffffu, v, 1);
        if (tg == 0) {
            int r = wm * 32 + (k >> 1) * 16 + (k & 1) * 8 + g;
            lj_s[r * 8 + wn] = v;
        }
    }
    __syncthreads();
    if (tid < MT) {
        float v = 0.f;
        #pragma unroll
        for (int j = 0; j < 8; j++) v += lj_s[tid * 8 + j];
        out[(size_t)NROWS * DD + row0 + tid] = v;
    }
}

extern "C" void kernel_launch(void* const* d_in, const int* in_sizes, int n_in,
                              void* d_out, int out_size)
{
    const float* z   = (const float*)d_in[0];
    const float* Ws1 = (const float*)d_in[1];
    const float* bs1 = (const float*)d_in[2];
    const float* Ws2 = (const float*)d_in[3];
    const float* bs2 = (const float*)d_in[4];
    const float* Wt1 = (const float*)d_in[5];
    const float* bt1 = (const float*)d_in[6];
    const float* Wt2 = (const float*)d_in[7];
    const float* bt2 = (const float*)d_in[8];
    float* out = (float*)d_out;

    static bool attr_set = false;
    if (!attr_set) {
        cudaFuncSetAttribute(nvp_main, cudaFuncAttributeMaxDynamicSharedMemorySize, SM_TOT);
        attr_set = true;
    }

    // 1) transpose + fp16-pack weights into [n][k] (deterministic, every call)
    pack_w<<<dim3(8, 8, 32), dim3(32, 8)>>>(Ws1, Ws2, Wt1, Wt2);

    // 2) fused 8-layer RealNVP (legacy HMMA, smem-staged weights, 16 warps)
    nvp_main<<<NCTAS, THREADS, SM_TOT>>>(z, bs1, bs2, bt1, bt2, out);
}

// round 7
// speedup vs baseline: 1.6883x; 1.5088x over previous
#include <cuda_runtime.h>
#include <cuda_fp16.h>
#include <cstdint>

// Problem constants
#define NROWS 65536
#define DD    512
#define NL    8
#define HH    256
#define HALFD 256

// Tiling: 8 warps = 2 (M) x 4 (N); warp tile 32x64
#define MT      64
#define THREADS 256
#define LDE     264     // half-elem leading dim for e/h tiles
#define LDO     260     // float leading dim for o/es tiles

// Packed fp16 weights in mma-B-fragment order:
// [layer][mat(4: Ws1,Ws2,Wt1,Wt2)][kstep 16][ntile 32][lane 32] as uint2 {b0b1, b2b3}
__device__ uint2 g_wpack[NL * 4 * 16 * 32 * 32];

__global__ void pack_w(const float* __restrict__ Ws1, const float* __restrict__ Ws2,
                       const float* __restrict__ Wt1, const float* __restrict__ Wt2)
{
    int idx = blockIdx.x * blockDim.x + threadIdx.x;
    if (idx >= NL * 4 * 16 * 32 * 32) return;
    int lane  = idx & 31;
    int nt    = (idx >> 5) & 31;
    int ks    = (idx >> 10) & 15;
    int mat   = (idx >> 14) & 3;
    int layer = idx >> 16;
    const float* W = (mat == 0) ? Ws1 : (mat == 1) ? Ws2 : (mat == 2) ? Wt1 : Wt2;
    W += (size_t)layer * HH * HALFD;   // every matrix is 256x256 [K][N] row-major
    int n  = nt * 8 + (lane >> 2);
    int k0 = ks * 16 + (lane & 3) * 2;
    __half2 p0 = __floats2half2_rn(W[k0 * 256 + n],       W[(k0 + 1) * 256 + n]);
    __half2 p1 = __floats2half2_rn(W[(k0 + 8) * 256 + n], W[(k0 + 9) * 256 + n]);
    uint2 v;
    v.x = *reinterpret_cast<uint32_t*>(&p0);
    v.y = *reinterpret_cast<uint32_t*>(&p1);
    g_wpack[idx] = v;
}

__device__ __forceinline__ void mma16816(float c[4], const uint32_t a[4], uint32_t b0, uint32_t b1)
{
    asm volatile(
        "mma.sync.aligned.m16n8k16.row.col.f32.f16.f16.f32 "
        "{%0,%1,%2,%3},{%4,%5,%6,%7},{%8,%9},{%0,%1,%2,%3};\n"
        : "+f"(c[0]), "+f"(c[1]), "+f"(c[2]), "+f"(c[3])
        : "r"(a[0]), "r"(a[1]), "r"(a[2]), "r"(a[3]), "r"(b0), "r"(b1));
}

__device__ __forceinline__ void ldmA(uint32_t a[4], uint32_t addr)
{
    asm volatile(
        "ldmatrix.sync.aligned.m8n8.x4.shared.b16 {%0,%1,%2,%3},[%4];\n"
        : "=r"(a[0]), "=r"(a[1]), "=r"(a[2]), "=r"(a[3])
        : "r"(addr));
}

// C = A(64x256, f16 smem, LDE) @ W(256x256 packed) ; warp tile 32x64
__device__ __forceinline__ void gemm_tile(uint32_t aBase, const uint2* __restrict__ wp,
                                          float acc[2][8][4],
                                          int lane, int wm, int wn, int rowoff, int koff)
{
    #pragma unroll
    for (int mt = 0; mt < 2; mt++)
        #pragma unroll
        for (int nt = 0; nt < 8; nt++)
            #pragma unroll
            for (int q = 0; q < 4; q++) acc[mt][nt][q] = 0.f;

    const uint32_t a0 = aBase + (uint32_t)((wm * 32 + rowoff) * LDE + koff) * 2;

    uint2 b[8];
    #pragma unroll
    for (int nt = 0; nt < 8; nt++) b[nt] = wp[(wn * 8 + nt) * 32 + lane];

    #pragma unroll
    for (int ks = 0; ks < 16; ks++) {
        // issue next-kstep B prefetch first so it overlaps this kstep's math
        uint2 bn[8];
        if (ks < 15) {
            #pragma unroll
            for (int nt = 0; nt < 8; nt++)
                bn[nt] = wp[((ks + 1) * 32 + wn * 8 + nt) * 32 + lane];
        }

        uint32_t a[2][4];
        #pragma unroll
        for (int mt = 0; mt < 2; mt++)
            ldmA(a[mt], a0 + mt * (16 * LDE * 2) + ks * 32);

        #pragma unroll
        for (int mt = 0; mt < 2; mt++)
            #pragma unroll
            for (int nt = 0; nt < 8; nt++)
                mma16816(acc[mt][nt], a[mt], b[nt].x, b[nt].y);

        if (ks < 15) {
            #pragma unroll
            for (int nt = 0; nt < 8; nt++) b[nt] = bn[nt];
        }
    }
}

__device__ __forceinline__ float tanh_acc(float x)
{
    x = fminf(fmaxf(x, -15.f), 15.f);
    float e2 = __expf(2.f * x);
    return __fdividef(e2 - 1.f, e2 + 1.f);
}

// SMEM layout (bytes)
#define SM_E   0
#define SM_H   (MT * LDE * 2)                 // 33792
#define SM_O   (SM_H + MT * LDE * 2)          // 67584
#define SM_S   (SM_O + MT * LDO * 4)          // 134144  (holds exp(s), f32)
#define SM_LJ  (SM_S + MT * LDO * 4)          // 200704
#define SM_TOT (SM_LJ + MT * 4 * 4)           // 201728

__global__ void __launch_bounds__(THREADS, 1) nvp_main(
    const float* __restrict__ z,
    const float* __restrict__ bs1, const float* __restrict__ bs2,
    const float* __restrict__ bt1, const float* __restrict__ bt2,
    float* __restrict__ out)
{
    extern __shared__ char smraw[];
    __half* e_s  = reinterpret_cast<__half*>(smraw + SM_E);
    __half* h_s  = reinterpret_cast<__half*>(smraw + SM_H);
    float*  o_s  = reinterpret_cast<float*>(smraw + SM_O);
    float*  s_s  = reinterpret_cast<float*>(smraw + SM_S);
    float*  lj_s = reinterpret_cast<float*>(smraw + SM_LJ);

    const int tid  = threadIdx.x;
    const int row0 = blockIdx.x * MT;

    // Load: z row -> (e f16 smem, o f32 smem); even half of output is the identity copy.
    for (int idx = tid; idx < MT * 256; idx += THREADS) {
        int r = idx >> 8, c = idx & 255;
        float2 p = reinterpret_cast<const float2*>(z + (size_t)(row0 + r) * DD)[c];
        e_s[r * LDE + c] = __float2half_rn(p.x);
        o_s[r * LDO + c] = p.y;
        out[(size_t)(row0 + r) * DD + c] = p.x;
    }
    __syncthreads();

    const int warp = tid >> 5, lane = tid & 31;
    const int wm = warp & 1, wn = warp >> 1;      // 2 x 4 warp grid, tile 32x64
    const int g = lane >> 2, tg = lane & 3;
    const int mat = lane >> 3, within = lane & 7;
    const int rowoff = ((mat & 1) << 3) + within; // ldmatrix per-lane row
    const int koff   = (mat >> 1) << 3;
    const uint32_t aE = (uint32_t)__cvta_generic_to_shared(e_s);
    const uint32_t aH = (uint32_t)__cvta_generic_to_shared(h_s);

    float lj[4] = {0.f, 0.f, 0.f, 0.f};
    float acc[2][8][4];

    for (int layer = 0; layer < NL; layer++) {
        const uint2* wl = g_wpack + (size_t)(layer * 4) * 16384;

        // ---------- s-MLP: h = relu(e @ Ws1 + bs1) ----------
        gemm_tile(aE, wl, acc, lane, wm, wn, rowoff, koff);
        __syncthreads();   // previous readers of h_s are done
        #pragma unroll
        for (int mt = 0; mt < 2; mt++)
            #pragma unroll
            for (int nt = 0; nt < 8; nt++) {
                int col0 = wn * 64 + nt * 8 + tg * 2;
                float2 bb = *reinterpret_cast<const float2*>(bs1 + layer * HH + col0);
                int r0 = wm * 32 + mt * 16 + g;
                __half2 v0 = __floats2half2_rn(fmaxf(acc[mt][nt][0] + bb.x, 0.f),
                                               fmaxf(acc[mt][nt][1] + bb.y, 0.f));
                __half2 v1 = __floats2half2_rn(fmaxf(acc[mt][nt][2] + bb.x, 0.f),
                                               fmaxf(acc[mt][nt][3] + bb.y, 0.f));
                *reinterpret_cast<__half2*>(h_s + r0 * LDE + col0)       = v0;
                *reinterpret_cast<__half2*>(h_s + (r0 + 8) * LDE + col0) = v1;
            }
        __syncthreads();

        // ---------- s = tanh(h @ Ws2 + bs2) ; store exp(s) ; lj += s ----------
        gemm_tile(aH, wl + 16384, acc, lane, wm, wn, rowoff, koff);
        #pragma unroll
        for (int mt = 0; mt < 2; mt++)
            #pragma unroll
            for (int nt = 0; nt < 8; nt++) {
                int col0 = wn * 64 + nt * 8 + tg * 2;
                float2 bb = *reinterpret_cast<const float2*>(bs2 + layer * HALFD + col0);
                int r0 = wm * 32 + mt * 16 + g;
                float s0 = tanh_acc(acc[mt][nt][0] + bb.x);
                float s1 = tanh_acc(acc[mt][nt][1] + bb.y);
                float s2 = tanh_acc(acc[mt][nt][2] + bb.x);
                float s3 = tanh_acc(acc[mt][nt][3] + bb.y);
                lj[mt * 2]     += s0 + s1;
                lj[mt * 2 + 1] += s2 + s3;
                *reinterpret_cast<float2*>(s_s + r0 * LDO + col0)
                    = make_float2(__expf(s0), __expf(s1));
                *reinterpret_cast<float2*>(s_s + (r0 + 8) * LDO + col0)
                    = make_float2(__expf(s2), __expf(s3));
            }
        __syncthreads();  // all warps done reading h_s (s-GEMM2)

        // ---------- t-MLP: h = relu(e @ Wt1 + bt1) ----------
        gemm_tile(aE, wl + 2 * 16384, acc, lane, wm, wn, rowoff, koff);
        #pragma unroll
        for (int mt = 0; mt < 2; mt++)
            #pragma unroll
            for (int nt = 0; nt < 8; nt++) {
                int col0 = wn * 64 + nt * 8 + tg * 2;
                float2 bb = *reinterpret_cast<const float2*>(bt1 + layer * HH + col0);
                int r0 = wm * 32 + mt * 16 + g;
                __half2 v0 = __floats2half2_rn(fmaxf(acc[mt][nt][0] + bb.x, 0.f),
                                               fmaxf(acc[mt][nt][1] + bb.y, 0.f));
                __half2 v1 = __floats2half2_rn(fmaxf(acc[mt][nt][2] + bb.x, 0.f),
                                               fmaxf(acc[mt][nt][3] + bb.y, 0.f));
                *reinterpret_cast<__half2*>(h_s + r0 * LDE + col0)       = v0;
                *reinterpret_cast<__half2*>(h_s + (r0 + 8) * LDE + col0) = v1;
            }
        __syncthreads();

        // ---------- t = h @ Wt2 + bt2 ; o = exp(s)*o + t ----------
        gemm_tile(aH, wl + 3 * 16384, acc, lane, wm, wn, rowoff, koff);
        #pragma unroll
        for (int mt = 0; mt < 2; mt++)
            #pragma unroll
            for (int nt = 0; nt < 8; nt++) {
                int col0 = wn * 64 + nt * 8 + tg * 2;
                float2 bb = *reinterpret_cast<const float2*>(bt2 + layer * HALFD + col0);
                int r0 = wm * 32 + mt * 16 + g;
                float2 ea = *reinterpret_cast<float2*>(s_s + r0 * LDO + col0);
                float2 eb = *reinterpret_cast<float2*>(s_s + (r0 + 8) * LDO + col0);
                float2 oa = *reinterpret_cast<float2*>(o_s + r0 * LDO + col0);
                float2 ob = *reinterpret_cast<float2*>(o_s + (r0 + 8) * LDO + col0);
                oa.x = ea.x * oa.x + acc[mt][nt][0] + bb.x;
                oa.y = ea.y * oa.y + acc[mt][nt][1] + bb.y;
                ob.x = eb.x * ob.x + acc[mt][nt][2] + bb.x;
                ob.y = eb.y * ob.y + acc[mt][nt][3] + bb.y;
                *reinterpret_cast<float2*>(o_s + r0 * LDO + col0)       = oa;
                *reinterpret_cast<float2*>(o_s + (r0 + 8) * LDO + col0) = ob;
            }
        // next layer's post-GEMM1 sync protects h_s; o_s/s_s are thread-private positions
    }
    __syncthreads();

    // Odd half of output
    for (int idx = tid; idx < MT * 256; idx += THREADS) {
        int r = idx >> 8, c = idx & 255;
        out[(size_t)(row0 + r) * DD + 256 + c] = o_s[r * LDO + c];
    }

    // Deterministic logjac reduction: intra-warp over tg, then across the 4 n-warps.
    #pragma unroll
    for (int k = 0; k < 4; k++) {
        float v = lj[k];
        v += __shfl_down_sync(0xffffffffu, v, 2);
        v += __shfl_down_sync(0xffffffffu, v, 1);
        if (tg == 0) {
            int r = wm * 32 + (k >> 1) * 16 + (k & 1) * 8 + g;
            lj_s[r * 4 + wn] = v;
        }
    }
    __syncthreads();
    if (tid < MT) {
        float v = 0.f;
        #pragma unroll
        for (int j = 0; j < 4; j++) v += lj_s[tid * 4 + j];
        out[(size_t)NROWS * DD + row0 + tid] = v;
    }
}

extern "C" void kernel_launch(void* const* d_in, const int* in_sizes, int n_in,
                              void* d_out, int out_size)
{
    const float* z   = (const float*)d_in[0];
    const float* Ws1 = (const float*)d_in[1];
    const float* bs1 = (const float*)d_in[2];
    const float* Ws2 = (const float*)d_in[3];
    const float* bs2 = (const float*)d_in[4];
    const float* Wt1 = (const float*)d_in[5];
    const float* bt1 = (const float*)d_in[6];
    const float* Wt2 = (const float*)d_in[7];
    const float* bt2 = (const float*)d_in[8];
    float* out = (float*)d_out;

    static bool attr_set = false;
    if (!attr_set) {
        cudaFuncSetAttribute(nvp_main, cudaFuncAttributeMaxDynamicSharedMemorySize, SM_TOT);
        attr_set = true;
    }

    // 1) pack weights to fragment-native fp16 (runs every call; deterministic)
    pack_w<<<(NL * 4 * 16 * 32 * 32 + 255) / 256, 256>>>(Ws1, Ws2, Wt1, Wt2);

    // 2) fused 8-layer RealNVP (legacy HMMA, warp tile 32x64, barrier-free mainloop)
    nvp_main<<<NROWS / MT, THREADS, SM_TOT>>>(z, bs1, bs2, bt1, bt2, out);
}

// round 8
// speedup vs baseline: 1.7311x; 1.0254x over previous
#include <cuda_runtime.h>
#include <cuda_fp16.h>
#include <cstdint>

// Problem constants
#define NROWS 65536
#define DD    512
#define NL    8
#define HH    256
#define HALFD 256

// Tiling: 8 warps = 2 (M) x 4 (N); warp tile 32x64
#define MT      64
#define THREADS 256
#define LDE     264     // half-elem leading dim for e/h tiles
#define LDO     260     // float leading dim for o/es tiles

// Packed fp16 weights, kpair-fused mma-B-fragment order:
// [layer][mat 4][kpair 8][ntile 32][lane 32] as uint4:
//   .x,.y = kstep 2*kp   fragments (b0b1, b2b3)
//   .z,.w = kstep 2*kp+1 fragments
__device__ uint4 g_wpack[NL * 4 * 8 * 32 * 32];

__global__ void pack_w(const float* __restrict__ Ws1, const float* __restrict__ Ws2,
                       const float* __restrict__ Wt1, const float* __restrict__ Wt2)
{
    int idx = blockIdx.x * blockDim.x + threadIdx.x;
    if (idx >= NL * 4 * 8 * 32 * 32) return;
    int lane  = idx & 31;
    int nt    = (idx >> 5) & 31;
    int kp    = (idx >> 10) & 7;
    int mat   = (idx >> 13) & 3;
    int layer = idx >> 15;
    const float* W = (mat == 0) ? Ws1 : (mat == 1) ? Ws2 : (mat == 2) ? Wt1 : Wt2;
    W += (size_t)layer * HH * HALFD;   // every matrix is 256x256 [K][N] row-major
    int n  = nt * 8 + (lane >> 2);
    int k0 = kp * 32 + (lane & 3) * 2;
    __half2 p0 = __floats2half2_rn(W[(k0     ) * 256 + n], W[(k0 +  1) * 256 + n]);
    __half2 p1 = __floats2half2_rn(W[(k0 +  8) * 256 + n], W[(k0 +  9) * 256 + n]);
    __half2 p2 = __floats2half2_rn(W[(k0 + 16) * 256 + n], W[(k0 + 17) * 256 + n]);
    __half2 p3 = __floats2half2_rn(W[(k0 + 24) * 256 + n], W[(k0 + 25) * 256 + n]);
    uint4 v;
    v.x = *reinterpret_cast<uint32_t*>(&p0);
    v.y = *reinterpret_cast<uint32_t*>(&p1);
    v.z = *reinterpret_cast<uint32_t*>(&p2);
    v.w = *reinterpret_cast<uint32_t*>(&p3);
    g_wpack[idx] = v;
}

__device__ __forceinline__ void mma16816(float c[4], const uint32_t a[4], uint32_t b0, uint32_t b1)
{
    asm volatile(
        "mma.sync.aligned.m16n8k16.row.col.f32.f16.f16.f32 "
        "{%0,%1,%2,%3},{%4,%5,%6,%7},{%8,%9},{%0,%1,%2,%3};\n"
        : "+f"(c[0]), "+f"(c[1]), "+f"(c[2]), "+f"(c[3])
        : "r"(a[0]), "r"(a[1]), "r"(a[2]), "r"(a[3]), "r"(b0), "r"(b1));
}

__device__ __forceinline__ void ldmA(uint32_t a[4], uint32_t addr)
{
    asm volatile(
        "ldmatrix.sync.aligned.m8n8.x4.shared.b16 {%0,%1,%2,%3},[%4];\n"
        : "=r"(a[0]), "=r"(a[1]), "=r"(a[2]), "=r"(a[3])
        : "r"(addr));
}

// C = A(64x256, f16 smem, LDE) @ W(256x256 packed) ; warp tile 32x64
// B prefetched one kpair (2 ksteps) ahead via LDG.128 -> covers L2 latency.
__device__ __forceinline__ void gemm_tile(uint32_t aBase, const uint4* __restrict__ wp,
                                          float acc[2][8][4],
                                          int lane, int wm, int wn, int rowoff, int koff)
{
    #pragma unroll
    for (int mt = 0; mt < 2; mt++)
        #pragma unroll
        for (int nt = 0; nt < 8; nt++)
            #pragma unroll
            for (int q = 0; q < 4; q++) acc[mt][nt][q] = 0.f;

    const uint32_t a0 = aBase + (uint32_t)((wm * 32 + rowoff) * LDE + koff) * 2;
    const uint4* wlane = wp + (wn * 8) * 32 + lane;

    uint4 b[2][8];
    #pragma unroll
    for (int nt = 0; nt < 8; nt++) b[0][nt] = wlane[nt * 32];

    #pragma unroll
    for (int kp = 0; kp < 8; kp++) {
        // prefetch next kpair's fragments (one full kpair of math covers the latency)
        if (kp < 7) {
            #pragma unroll
            for (int nt = 0; nt < 8; nt++)
                b[(kp + 1) & 1][nt] = wlane[((kp + 1) * 32 + nt) * 32];
        }
        // kstep even = 2*kp : uses .x,.y
        {
            uint32_t a[2][4];
            ldmA(a[0], a0 + (2 * kp) * 32);
            ldmA(a[1], a0 + (2 * kp) * 32 + 16 * LDE * 2);
            #pragma unroll
            for (int mt = 0; mt < 2; mt++)
                #pragma unroll
                for (int nt = 0; nt < 8; nt++)
                    mma16816(acc[mt][nt], a[mt], b[kp & 1][nt].x, b[kp & 1][nt].y);
        }
        // kstep odd = 2*kp+1 : uses .z,.w
        {
            uint32_t a[2][4];
            ldmA(a[0], a0 + (2 * kp + 1) * 32);
            ldmA(a[1], a0 + (2 * kp + 1) * 32 + 16 * LDE * 2);
            #pragma unroll
            for (int mt = 0; mt < 2; mt++)
                #pragma unroll
                for (int nt = 0; nt < 8; nt++)
                    mma16816(acc[mt][nt], a[mt], b[kp & 1][nt].z, b[kp & 1][nt].w);
        }
    }
}

__device__ __forceinline__ float tanh_acc(float x)
{
    x = fminf(fmaxf(x, -15.f), 15.f);
    float e2 = __expf(2.f * x);
    return __fdividef(e2 - 1.f, e2 + 1.f);
}

// SMEM layout (bytes)
#define SM_E   0
#define SM_H   (MT * LDE * 2)                 // 33792
#define SM_O   (SM_H + MT * LDE * 2)          // 67584
#define SM_S   (SM_O + MT * LDO * 4)          // 134144  (holds exp(s), f32)
#define SM_LJ  (SM_S + MT * LDO * 4)          // 200704
#define SM_TOT (SM_LJ + MT * 4 * 4)           // 201728

__global__ void __launch_bounds__(THREADS, 1) nvp_main(
    const float* __restrict__ z,
    const float* __restrict__ bs1, const float* __restrict__ bs2,
    const float* __restrict__ bt1, const float* __restrict__ bt2,
    float* __restrict__ out)
{
    extern __shared__ char smraw[];
    __half* e_s  = reinterpret_cast<__half*>(smraw + SM_E);
    __half* h_s  = reinterpret_cast<__half*>(smraw + SM_H);
    float*  o_s  = reinterpret_cast<float*>(smraw + SM_O);
    float*  s_s  = reinterpret_cast<float*>(smraw + SM_S);
    float*  lj_s = reinterpret_cast<float*>(smraw + SM_LJ);

    const int tid  = threadIdx.x;
    const int row0 = blockIdx.x * MT;

    // Load: z row -> (e f16 smem, o f32 smem); even half of output is the identity copy.
    for (int idx = tid; idx < MT * 256; idx += THREADS) {
        int r = idx >> 8, c = idx & 255;
        float2 p = reinterpret_cast<const float2*>(z + (size_t)(row0 + r) * DD)[c];
        e_s[r * LDE + c] = __float2half_rn(p.x);
        o_s[r * LDO + c] = p.y;
        out[(size_t)(row0 + r) * DD + c] = p.x;
    }
    __syncthreads();

    const int warp = tid >> 5, lane = tid & 31;
    const int wm = warp & 1, wn = warp >> 1;      // 2 x 4 warp grid, tile 32x64
    const int g = lane >> 2, tg = lane & 3;
    const int mat = lane >> 3, within = lane & 7;
    const int rowoff = ((mat & 1) << 3) + within; // ldmatrix per-lane row
    const int koff   = (mat >> 1) << 3;
    const uint32_t aE = (uint32_t)__cvta_generic_to_shared(e_s);
    const uint32_t aH = (uint32_t)__cvta_generic_to_shared(h_s);

    float lj[4] = {0.f, 0.f, 0.f, 0.f};
    float acc[2][8][4];

    for (int layer = 0; layer < NL; layer++) {
        const uint4* wl = g_wpack + (size_t)(layer * 4) * 8192;

        // ---------- s-MLP: h = relu(e @ Ws1 + bs1) ----------
        gemm_tile(aE, wl, acc, lane, wm, wn, rowoff, koff);
        __syncthreads();   // previous readers of h_s are done
        #pragma unroll
        for (int mt = 0; mt < 2; mt++)
            #pragma unroll
            for (int nt = 0; nt < 8; nt++) {
                int col0 = wn * 64 + nt * 8 + tg * 2;
                float2 bb = *reinterpret_cast<const float2*>(bs1 + layer * HH + col0);
                int r0 = wm * 32 + mt * 16 + g;
                __half2 v0 = __floats2half2_rn(fmaxf(acc[mt][nt][0] + bb.x, 0.f),
                                               fmaxf(acc[mt][nt][1] + bb.y, 0.f));
                __half2 v1 = __floats2half2_rn(fmaxf(acc[mt][nt][2] + bb.x, 0.f),
                                               fmaxf(acc[mt][nt][3] + bb.y, 0.f));
                *reinterpret_cast<__half2*>(h_s + r0 * LDE + col0)       = v0;
                *reinterpret_cast<__half2*>(h_s + (r0 + 8) * LDE + col0) = v1;
            }
        __syncthreads();

        // ---------- s = tanh(h @ Ws2 + bs2) ; store exp(s) ; lj += s ----------
        gemm_tile(aH, wl + 8192, acc, lane, wm, wn, rowoff, koff);
        #pragma unroll
        for (int mt = 0; mt < 2; mt++)
            #pragma unroll
            for (int nt = 0; nt < 8; nt++) {
                int col0 = wn * 64 + nt * 8 + tg * 2;
                float2 bb = *reinterpret_cast<const float2*>(bs2 + layer * HALFD + col0);
                int r0 = wm * 32 + mt * 16 + g;
                float s0 = tanh_acc(acc[mt][nt][0] + bb.x);
                float s1 = tanh_acc(acc[mt][nt][1] + bb.y);
                float s2 = tanh_acc(acc[mt][nt][2] + bb.x);
                float s3 = tanh_acc(acc[mt][nt][3] + bb.y);
                lj[mt * 2]     += s0 + s1;
                lj[mt * 2 + 1] += s2 + s3;
                *reinterpret_cast<float2*>(s_s + r0 * LDO + col0)
                    = make_float2(__expf(s0), __expf(s1));
                *reinterpret_cast<float2*>(s_s + (r0 + 8) * LDO + col0)
                    = make_float2(__expf(s2), __expf(s3));
            }
        __syncthreads();  // all warps done reading h_s (s-GEMM2)

        // ---------- t-MLP: h = relu(e @ Wt1 + bt1) ----------
        gemm_tile(aE, wl + 2 * 8192, acc, lane, wm, wn, rowoff, koff);
        #pragma unroll
        for (int mt = 0; mt < 2; mt++)
            #pragma unroll
            for (int nt = 0; nt < 8; nt++) {
                int col0 = wn * 64 + nt * 8 + tg * 2;
                float2 bb = *reinterpret_cast<const float2*>(bt1 + layer * HH + col0);
                int r0 = wm * 32 + mt * 16 + g;
                __half2 v0 = __floats2half2_rn(fmaxf(acc[mt][nt][0] + bb.x, 0.f),
                                               fmaxf(acc[mt][nt][1] + bb.y, 0.f));
                __half2 v1 = __floats2half2_rn(fmaxf(acc[mt][nt][2] + bb.x, 0.f),
                                               fmaxf(acc[mt][nt][3] + bb.y, 0.f));
                *reinterpret_cast<__half2*>(h_s + r0 * LDE + col0)       = v0;
                *reinterpret_cast<__half2*>(h_s + (r0 + 8) * LDE + col0) = v1;
            }
        __syncthreads();

        // ---------- t = h @ Wt2 + bt2 ; o = exp(s)*o + t ----------
        gemm_tile(aH, wl + 3 * 8192, acc, lane, wm, wn, rowoff, koff);
        #pragma unroll
        for (int mt = 0; mt < 2; mt++)
            #pragma unroll
            for (int nt = 0; nt < 8; nt++) {
                int col0 = wn * 64 + nt * 8 + tg * 2;
                float2 bb = *reinterpret_cast<const float2*>(bt2 + layer * HALFD + col0);
                int r0 = wm * 32 + mt * 16 + g;
                float2 ea = *reinterpret_cast<float2*>(s_s + r0 * LDO + col0);
                float2 eb = *reinterpret_cast<float2*>(s_s + (r0 + 8) * LDO + col0);
                float2 oa = *reinterpret_cast<float2*>(o_s + r0 * LDO + col0);
                float2 ob = *reinterpret_cast<float2*>(o_s + (r0 + 8) * LDO + col0);
                oa.x = ea.x * oa.x + acc[mt][nt][0] + bb.x;
                oa.y = ea.y * oa.y + acc[mt][nt][1] + bb.y;
                ob.x = eb.x * ob.x + acc[mt][nt][2] + bb.x;
                ob.y = eb.y * ob.y + acc[mt][nt][3] + bb.y;
                *reinterpret_cast<float2*>(o_s + r0 * LDO + col0)       = oa;
                *reinterpret_cast<float2*>(o_s + (r0 + 8) * LDO + col0) = ob;
            }
        // next layer's post-GEMM1 sync protects h_s; o_s/s_s are thread-private positions
    }
    __syncthreads();

    // Odd half of output
    for (int idx = tid; idx < MT * 256; idx += THREADS) {
        int r = idx >> 8, c = idx & 255;
        out[(size_t)(row0 + r) * DD + 256 + c] = o_s[r * LDO + c];
    }

    // Deterministic logjac reduction: intra-warp over tg, then across the 4 n-warps.
    #pragma unroll
    for (int k = 0; k < 4; k++) {
        float v = lj[k];
        v += __shfl_down_sync(0xffffffffu, v, 2);
        v += __shfl_down_sync(0xffffffffu, v, 1);
        if (tg == 0) {
            int r = wm * 32 + (k >> 1) * 16 + (k & 1) * 8 + g;
            lj_s[r * 4 + wn] = v;
        }
    }
    __syncthreads();
    if (tid < MT) {
        float v = 0.f;
        #pragma unroll
        for (int j = 0; j < 4; j++) v += lj_s[tid * 4 + j];
        out[(size_t)NROWS * DD + row0 + tid] = v;
    }
}

extern "C" void kernel_launch(void* const* d_in, const int* in_sizes, int n_in,
                              void* d_out, int out_size)
{
    const float* z   = (const float*)d_in[0];
    const float* Ws1 = (const float*)d_in[1];
    const float* bs1 = (const float*)d_in[2];
    const float* Ws2 = (const float*)d_in[3];
    const float* bs2 = (const float*)d_in[4];
    const float* Wt1 = (const float*)d_in[5];
    const float* bt1 = (const float*)d_in[6];
    const float* Wt2 = (const float*)d_in[7];
    const float* bt2 = (const float*)d_in[8];
    float* out = (float*)d_out;

    static bool attr_set = false;
    if (!attr_set) {
        cudaFuncSetAttribute(nvp_main, cudaFuncAttributeMaxDynamicSharedMemorySize, SM_TOT);
        attr_set = true;
    }

    // 1) pack weights: kpair-fused fragment layout (LDG.128, distance = 1 kpair)
    pack_w<<<(NL * 4 * 8 * 32 * 32 + 255) / 256, 256>>>(Ws1, Ws2, Wt1, Wt2);

    // 2) fused 8-layer RealNVP (legacy HMMA, warp tile 32x64, kpair-deep B prefetch)
    nvp_main<<<NROWS / MT, THREADS, SM_TOT>>>(z, bs1, bs2, bt1, bt2, out);
}

// round 11
// speedup vs baseline: 1.8742x; 1.0827x over previous
#include <cuda_runtime.h>
#include <cuda_fp16.h>
#include <cstdint>

// Problem constants
#define NROWS 65536
#define DD    512
#define NL    8
#define HH    256
#define HALFD 256

// Tiling: MT=32 rows/CTA, 8 warps all along N; warp tile 32(M) x 32(N).
// Small smem footprint -> 2 CTAs/SM -> epilogues of one CTA overlap GEMMs of the other.
#define MT      32
#define THREADS 256
#define NCTAS   (NROWS / MT)   // 2048
#define LDE     264            // halfs, leading dim of e/h tiles
#define LDO     260            // floats, leading dim of o/s tiles

// Packed fp16 weights, kpair-fused mma-B-fragment order:
// [layer][mat 4][kpair 8][ntile 32][lane 32] as uint4:
//   .x,.y = kstep 2*kp   fragments (b0b1, b2b3)
//   .z,.w = kstep 2*kp+1 fragments
__device__ uint4 g_wpack[NL * 4 * 8 * 32 * 32];

__global__ void pack_w(const float* __restrict__ Ws1, const float* __restrict__ Ws2,
                       const float* __restrict__ Wt1, const float* __restrict__ Wt2)
{
    int idx = blockIdx.x * blockDim.x + threadIdx.x;
    if (idx >= NL * 4 * 8 * 32 * 32) return;
    int lane  = idx & 31;
    int nt    = (idx >> 5) & 31;
    int kp    = (idx >> 10) & 7;
    int mat   = (idx >> 13) & 3;
    int layer = idx >> 15;
    const float* W = (mat == 0) ? Ws1 : (mat == 1) ? Ws2 : (mat == 2) ? Wt1 : Wt2;
    W += (size_t)layer * HH * HALFD;   // every matrix is 256x256 [K][N] row-major
    int n  = nt * 8 + (lane >> 2);
    int k0 = kp * 32 + (lane & 3) * 2;
    __half2 p0 = __floats2half2_rn(W[(k0     ) * 256 + n], W[(k0 +  1) * 256 + n]);
    __half2 p1 = __floats2half2_rn(W[(k0 +  8) * 256 + n], W[(k0 +  9) * 256 + n]);
    __half2 p2 = __floats2half2_rn(W[(k0 + 16) * 256 + n], W[(k0 + 17) * 256 + n]);
    __half2 p3 = __floats2half2_rn(W[(k0 + 24) * 256 + n], W[(k0 + 25) * 256 + n]);
    uint4 v;
    v.x = *reinterpret_cast<uint32_t*>(&p0);
    v.y = *reinterpret_cast<uint32_t*>(&p1);
    v.z = *reinterpret_cast<uint32_t*>(&p2);
    v.w = *reinterpret_cast<uint32_t*>(&p3);
    g_wpack[idx] = v;
}

__device__ __forceinline__ void mma16816(float c[4], const uint32_t a[4], uint32_t b0, uint32_t b1)
{
    asm volatile(
        "mma.sync.aligned.m16n8k16.row.col.f32.f16.f16.f32 "
        "{%0,%1,%2,%3},{%4,%5,%6,%7},{%8,%9},{%0,%1,%2,%3};\n"
        : "+f"(c[0]), "+f"(c[1]), "+f"(c[2]), "+f"(c[3])
        : "r"(a[0]), "r"(a[1]), "r"(a[2]), "r"(a[3]), "r"(b0), "r"(b1));
}

__device__ __forceinline__ void ldmA(uint32_t a[4], uint32_t addr)
{
    asm volatile(
        "ldmatrix.sync.aligned.m8n8.x4.shared.b16 {%0,%1,%2,%3},[%4];\n"
        : "=r"(a[0]), "=r"(a[1]), "=r"(a[2]), "=r"(a[3])
        : "r"(addr));
}

// C = A(32x256, f16 smem, LDE) @ W(256x256 packed) ; warp tile 32x32 ; fp32 accumulators.
// B prefetched one kpair ahead via LDG.128.
__device__ __forceinline__ void gemm_tile(uint32_t aBase, const uint4* __restrict__ wp,
                                          float acc[2][4][4],
                                          int lane, int wn, int rowoff, int koff)
{
    #pragma unroll
    for (int mt = 0; mt < 2; mt++)
        #pragma unroll
        for (int nt = 0; nt < 4; nt++)
            #pragma unroll
            for (int q = 0; q < 4; q++) acc[mt][nt][q] = 0.f;

    const uint32_t a0 = aBase + (uint32_t)(rowoff * LDE + koff) * 2;
    const uint4* wlane = wp + (wn * 4) * 32 + lane;

    uint4 b[2][4];
    #pragma unroll
    for (int nt = 0; nt < 4; nt++) b[0][nt] = wlane[nt * 32];

    #pragma unroll
    for (int kp = 0; kp < 8; kp++) {
        if (kp < 7) {
            #pragma unroll
            for (int nt = 0; nt < 4; nt++)
                b[(kp + 1) & 1][nt] = wlane[((kp + 1) * 32 + nt) * 32];
        }
        // kstep even = 2*kp : uses .x,.y
        {
            uint32_t a[2][4];
            ldmA(a[0], a0 + (2 * kp) * 32);
            ldmA(a[1], a0 + (2 * kp) * 32 + 16 * LDE * 2);
            #pragma unroll
            for (int mt = 0; mt < 2; mt++)
                #pragma unroll
                for (int nt = 0; nt < 4; nt++)
                    mma16816(acc[mt][nt], a[mt], b[kp & 1][nt].x, b[kp & 1][nt].y);
        }
        // kstep odd = 2*kp+1 : uses .z,.w
        {
            uint32_t a[2][4];
            ldmA(a[0], a0 + (2 * kp + 1) * 32);
            ldmA(a[1], a0 + (2 * kp + 1) * 32 + 16 * LDE * 2);
            #pragma unroll
            for (int mt = 0; mt < 2; mt++)
                #pragma unroll
                for (int nt = 0; nt < 4; nt++)
                    mma16816(acc[mt][nt], a[mt], b[kp & 1][nt].z, b[kp & 1][nt].w);
        }
    }
}

__device__ __forceinline__ float tanh_acc(float x)
{
    x = fminf(fmaxf(x, -15.f), 15.f);
    float e2 = __expf(2.f * x);
    return __fdividef(e2 - 1.f, e2 + 1.f);
}

// SMEM layout (bytes) -- ~99KB/CTA so two CTAs fit per SM
#define SM_E   0
#define SM_H   (MT * LDE * 2)                 // 16896
#define SM_O   (SM_H + MT * LDE * 2)          // 33792
#define SM_S   (SM_O + MT * LDO * 4)          // 67072  (holds exp(s), f32)
#define SM_LJ  (SM_S + MT * LDO * 4)          // 100352
#define SM_TOT (SM_LJ + MT * 8 * 4)           // 101376

__global__ void __launch_bounds__(THREADS, 2) nvp_main(
    const float* __restrict__ z,
    const float* __restrict__ bs1, const float* __restrict__ bs2,
    const float* __restrict__ bt1, const float* __restrict__ bt2,
    float* __restrict__ out)
{
    extern __shared__ char smraw[];
    __half* e_s  = reinterpret_cast<__half*>(smraw + SM_E);
    __half* h_s  = reinterpret_cast<__half*>(smraw + SM_H);
    float*  o_s  = reinterpret_cast<float*>(smraw + SM_O);
    float*  s_s  = reinterpret_cast<float*>(smraw + SM_S);
    float*  lj_s = reinterpret_cast<float*>(smraw + SM_LJ);

    const int tid  = threadIdx.x;
    const int row0 = blockIdx.x * MT;

    // Load: z row -> (e f16 smem, o f32 smem); even half of output is the identity copy.
    for (int idx = tid; idx < MT * 256; idx += THREADS) {
        int r = idx >> 8, c = idx & 255;
        float2 p = reinterpret_cast<const float2*>(z + (size_t)(row0 + r) * DD)[c];
        e_s[r * LDE + c] = __float2half_rn(p.x);
        o_s[r * LDO + c] = p.y;
        out[(size_t)(row0 + r) * DD + c] = p.x;
    }
    __syncthreads();

    const int warp = tid >> 5, lane = tid & 31;
    const int wn = warp;                          // 1 x 8 warp grid, warp tile 32x32
    const int g = lane >> 2, tg = lane & 3;
    const int mat = lane >> 3, within = lane & 7;
    const int rowoff = ((mat & 1) << 3) + within; // ldmatrix per-lane row
    const int koff   = (mat >> 1) << 3;
    const uint32_t aE = (uint32_t)__cvta_generic_to_shared(e_s);
    const uint32_t aH = (uint32_t)__cvta_generic_to_shared(h_s);

    float lj[4] = {0.f, 0.f, 0.f, 0.f};
    float acc[2][4][4];

    for (int layer = 0; layer < NL; layer++) {
        const uint4* wl = g_wpack + (size_t)(layer * 4) * 8192;

        // ---------- s-MLP: h = relu(e @ Ws1 + bs1) ----------
        gemm_tile(aE, wl, acc, lane, wn, rowoff, koff);
        __syncthreads();   // previous readers of h_s are done
        #pragma unroll
        for (int mt = 0; mt < 2; mt++)
            #pragma unroll
            for (int nt = 0; nt < 4; nt++) {
                int col0 = wn * 32 + nt * 8 + tg * 2;
                float2 bb = *reinterpret_cast<const float2*>(bs1 + layer * HH + col0);
                int r0 = mt * 16 + g;
                __half2 v0 = __floats2half2_rn(fmaxf(acc[mt][nt][0] + bb.x, 0.f),
                                               fmaxf(acc[mt][nt][1] + bb.y, 0.f));
                __half2 v1 = __floats2half2_rn(fmaxf(acc[mt][nt][2] + bb.x, 0.f),
                                               fmaxf(acc[mt][nt][3] + bb.y, 0.f));
                *reinterpret_cast<__half2*>(h_s + r0 * LDE + col0)       = v0;
                *reinterpret_cast<__half2*>(h_s + (r0 + 8) * LDE + col0) = v1;
            }
        __syncthreads();

        // ---------- s = tanh(h @ Ws2 + bs2) ; store exp(s) ; lj += s ----------
        gemm_tile(aH, wl + 8192, acc, lane, wn, rowoff, koff);
        #pragma unroll
        for (int mt = 0; mt < 2; mt++)
            #pragma unroll
            for (int nt = 0; nt < 4; nt++) {
                int col0 = wn * 32 + nt * 8 + tg * 2;
                float2 bb = *reinterpret_cast<const float2*>(bs2 + layer * HALFD + col0);
                int r0 = mt * 16 + g;
                float s0 = tanh_acc(acc[mt][nt][0] + bb.x);
                float s1 = tanh_acc(acc[mt][nt][1] + bb.y);
                float s2 = tanh_acc(acc[mt][nt][2] + bb.x);
                float s3 = tanh_acc(acc[mt][nt][3] + bb.y);
                lj[mt * 2]     += s0 + s1;
                lj[mt * 2 + 1] += s2 + s3;
                *reinterpret_cast<float2*>(s_s + r0 * LDO + col0)
                    = make_float2(__expf(s0), __expf(s1));
                *reinterpret_cast<float2*>(s_s + (r0 + 8) * LDO + col0)
                    = make_float2(__expf(s2), __expf(s3));
            }
        __syncthreads();  // all warps done reading h_s (s-GEMM2)

        // ---------- t-MLP: h = relu(e @ Wt1 + bt1) ----------
        gemm_tile(aE, wl + 2 * 8192, acc, lane, wn, rowoff, koff);
        #pragma unroll
        for (int mt = 0; mt < 2; mt++)
            #pragma unroll
            for (int nt = 0; nt < 4; nt++) {
                int col0 = wn * 32 + nt * 8 + tg * 2;
                float2 bb = *reinterpret_cast<const float2*>(bt1 + layer * HH + col0);
                int r0 = mt * 16 + g;
                __half2 v0 = __floats2half2_rn(fmaxf(acc[mt][nt][0] + bb.x, 0.f),
                                               fmaxf(acc[mt][nt][1] + bb.y, 0.f));
                __half2 v1 = __floats2half2_rn(fmaxf(acc[mt][nt][2] + bb.x, 0.f),
                                               fmaxf(acc[mt][nt][3] + bb.y, 0.f));
                *reinterpret_cast<__half2*>(h_s + r0 * LDE + col0)       = v0;
                *reinterpret_cast<__half2*>(h_s + (r0 + 8) * LDE + col0) = v1;
            }
        __syncthreads();

        // ---------- t = h @ Wt2 + bt2 ; o = exp(s)*o + t ----------
        gemm_tile(aH, wl + 3 * 8192, acc, lane, wn, rowoff, koff);
        #pragma unroll
        for (int mt = 0; mt < 2; mt++)
            #pragma unroll
            for (int nt = 0; nt < 4; nt++) {
                int col0 = wn * 32 + nt * 8 + tg * 2;
                float2 bb = *reinterpret_cast<const float2*>(bt2 + layer * HALFD + col0);
                int r0 = mt * 16 + g;
                float2 ea = *reinterpret_cast<float2*>(s_s + r0 * LDO + col0);
                float2 eb = *reinterpret_cast<float2*>(s_s + (r0 + 8) * LDO + col0);
                float2 oa = *reinterpret_cast<float2*>(o_s + r0 * LDO + col0);
                float2 ob = *reinterpret_cast<float2*>(o_s + (r0 + 8) * LDO + col0);
                oa.x = ea.x * oa.x + acc[mt][nt][0] + bb.x;
                oa.y = ea.y * oa.y + acc[mt][nt][1] + bb.y;
                ob.x = eb.x * ob.x + acc[mt][nt][2] + bb.x;
                ob.y = eb.y * ob.y + acc[mt][nt][3] + bb.y;
                *reinterpret_cast<float2*>(o_s + r0 * LDO + col0)       = oa;
                *reinterpret_cast<float2*>(o_s + (r0 + 8) * LDO + col0) = ob;
            }
        // next layer's post-GEMM1 sync protects h_s; o_s/s_s are thread-private positions
    }
    __syncthreads();

    // Odd half of output
    for (int idx = tid; idx < MT * 256; idx += THREADS) {
        int r = idx >> 8, c = idx & 255;
        out[(size_t)(row0 + r) * DD + 256 + c] = o_s[r * LDO + c];
    }

    // Deterministic logjac reduction: intra-warp over tg, then across the 8 n-warps.
    #pragma unroll
    for (int k = 0; k < 4; k++) {
        float v = lj[k];
        v += __shfl_down_sync(0xffffffffu, v, 2);
        v += __shfl_down_sync(0xffffffffu, v, 1);
        if (tg == 0) {
            int r = (k >> 1) * 16 + (k & 1) * 8 + g;
            lj_s[r * 8 + wn] = v;
        }
    }
    __syncthreads();
    if (tid < MT) {
        float v = 0.f;
        #pragma unroll
        for (int j = 0; j < 8; j++) v += lj_s[tid * 8 + j];
        out[(size_t)NROWS * DD + row0 + tid] = v;
    }
}

extern "C" void kernel_launch(void* const* d_in, const int* in_sizes, int n_in,
                              void* d_out, int out_size)
{
    const float* z   = (const float*)d_in[0];
    const float* Ws1 = (const float*)d_in[1];
    const float* bs1 = (const float*)d_in[2];
    const float* Ws2 = (const float*)d_in[3];
    const float* bs2 = (const float*)d_in[4];
    const float* Wt1 = (const float*)d_in[5];
    const float* bt1 = (const float*)d_in[6];
    const float* Wt2 = (const float*)d_in[7];
    const float* bt2 = (const float*)d_in[8];
    float* out = (float*)d_out;

    static bool attr_set = false;
    if (!attr_set) {
        cudaFuncSetAttribute(nvp_main, cudaFuncAttributeMaxDynamicSharedMemorySize, SM_TOT);
        attr_set = true;
    }

    // 1) pack weights: kpair-fused fragment layout (LDG.128)
    pack_w<<<(NL * 4 * 8 * 32 * 32 + 255) / 256, 256>>>(Ws1, Ws2, Wt1, Wt2);

    // 2) fused 8-layer RealNVP: MT=32, 2 CTAs/SM -> epilogue/GEMM overlap across CTAs
    nvp_main<<<NCTAS, THREADS, SM_TOT>>>(z, bs1, bs2, bt1, bt2, out);
}

// round 12
// speedup vs baseline: 2.0218x; 1.0788x over previous
#include <cuda_runtime.h>
#include <cuda_fp16.h>
#include <cstdint>

// Problem constants
#define NROWS 65536
#define DD    512
#define NL    8
#define HH    256
#define HALFD 256

// Tiling: MT=32 rows/CTA, 8 warps along N, 2 CTAs/SM.
// G1 fused: 32x512 output (warp tile 32x64); G2: 32x256 (warp tile 32x32).
#define MT      32
#define THREADS 256
#define NCTAS   (NROWS / MT)   // 2048
#define LDE     264            // halfs, leading dim of e tile
#define LDH     520            // halfs, leading dim of h tile (512 cols + pad)
#define LDO     260            // floats, leading dim of o tile

// Packed fp16 weights, kpair-fused mma-B-fragment order:
// [layer][mat 4][kpair 8][ntile 32][lane 32] as uint4:
//   .x,.y = kstep 2*kp fragments ; .z,.w = kstep 2*kp+1 fragments
__device__ uint4 g_wpack[NL * 4 * 8 * 32 * 32];

__global__ void pack_w(const float* __restrict__ Ws1, const float* __restrict__ Ws2,
                       const float* __restrict__ Wt1, const float* __restrict__ Wt2)
{
    int idx = blockIdx.x * blockDim.x + threadIdx.x;
    if (idx >= NL * 4 * 8 * 32 * 32) return;
    int lane  = idx & 31;
    int nt    = (idx >> 5) & 31;
    int kp    = (idx >> 10) & 7;
    int mat   = (idx >> 13) & 3;
    int layer = idx >> 15;
    const float* W = (mat == 0) ? Ws1 : (mat == 1) ? Ws2 : (mat == 2) ? Wt1 : Wt2;
    W += (size_t)layer * HH * HALFD;   // every matrix is 256x256 [K][N] row-major
    int n  = nt * 8 + (lane >> 2);
    int k0 = kp * 32 + (lane & 3) * 2;
    __half2 p0 = __floats2half2_rn(W[(k0     ) * 256 + n], W[(k0 +  1) * 256 + n]);
    __half2 p1 = __floats2half2_rn(W[(k0 +  8) * 256 + n], W[(k0 +  9) * 256 + n]);
    __half2 p2 = __floats2half2_rn(W[(k0 + 16) * 256 + n], W[(k0 + 17) * 256 + n]);
    __half2 p3 = __floats2half2_rn(W[(k0 + 24) * 256 + n], W[(k0 + 25) * 256 + n]);
    uint4 v;
    v.x = *reinterpret_cast<uint32_t*>(&p0);
    v.y = *reinterpret_cast<uint32_t*>(&p1);
    v.z = *reinterpret_cast<uint32_t*>(&p2);
    v.w = *reinterpret_cast<uint32_t*>(&p3);
    g_wpack[idx] = v;
}

__device__ __forceinline__ void mma16816(float c[4], const uint32_t a[4], uint32_t b0, uint32_t b1)
{
    asm volatile(
        "mma.sync.aligned.m16n8k16.row.col.f32.f16.f16.f32 "
        "{%0,%1,%2,%3},{%4,%5,%6,%7},{%8,%9},{%0,%1,%2,%3};\n"
        : "+f"(c[0]), "+f"(c[1]), "+f"(c[2]), "+f"(c[3])
        : "r"(a[0]), "r"(a[1]), "r"(a[2]), "r"(a[3]), "r"(b0), "r"(b1));
}

__device__ __forceinline__ void ldmA(uint32_t a[4], uint32_t addr)
{
    asm volatile(
        "ldmatrix.sync.aligned.m8n8.x4.shared.b16 {%0,%1,%2,%3},[%4];\n"
        : "=r"(a[0]), "=r"(a[1]), "=r"(a[2]), "=r"(a[3])
        : "r"(addr));
}

__device__ __forceinline__ float tanh_acc(float x)
{
    x = fminf(fmaxf(x, -15.f), 15.f);
    float e2 = __expf(2.f * x);
    return __fdividef(e2 - 1.f, e2 + 1.f);
}

// Fused layer-1 GEMM: this warp's 64-col slice of [Ws1|Wt1]; A = e (LDE), warp tile 32x64
__device__ __forceinline__ void gemm512(uint32_t aBase, const uint4* __restrict__ wlane,
                                        float acc[2][8][4], int rowoff, int koff)
{
    #pragma unroll
    for (int mt = 0; mt < 2; mt++)
        #pragma unroll
        for (int j = 0; j < 8; j++)
            #pragma unroll
            for (int q = 0; q < 4; q++) acc[mt][j][q] = 0.f;

    const uint32_t a0 = aBase + (uint32_t)(rowoff * LDE + koff) * 2;
    #pragma unroll
    for (int kp = 0; kp < 8; kp++) {
        uint4 b[8];
        #pragma unroll
        for (int j = 0; j < 8; j++) b[j] = wlane[kp * 1024 + j * 32];
        uint32_t a[2][4];
        ldmA(a[0], a0 + (2 * kp) * 32);
        ldmA(a[1], a0 + (2 * kp) * 32 + 16 * LDE * 2);
        #pragma unroll
        for (int mt = 0; mt < 2; mt++)
            #pragma unroll
            for (int j = 0; j < 8; j++)
                mma16816(acc[mt][j], a[mt], b[j].x, b[j].y);
        ldmA(a[0], a0 + (2 * kp + 1) * 32);
        ldmA(a[1], a0 + (2 * kp + 1) * 32 + 16 * LDE * 2);
        #pragma unroll
        for (int mt = 0; mt < 2; mt++)
            #pragma unroll
            for (int j = 0; j < 8; j++)
                mma16816(acc[mt][j], a[mt], b[j].z, b[j].w);
    }
}

// Layer-2 GEMM: A = h (LDH, k-offset kofs halfs), warp tile 32x32, double-buffered B
__device__ __forceinline__ void gemm256(uint32_t aBase, int kofs, const uint4* __restrict__ wlane,
                                        float acc[2][8][4], int rowoff, int koff)
{
    #pragma unroll
    for (int mt = 0; mt < 2; mt++)
        #pragma unroll
        for (int nt = 0; nt < 4; nt++)
            #pragma unroll
            for (int q = 0; q < 4; q++) acc[mt][nt][q] = 0.f;

    const uint32_t a0 = aBase + (uint32_t)(rowoff * LDH + kofs + koff) * 2;

    uint4 b[2][4];
    #pragma unroll
    for (int nt = 0; nt < 4; nt++) b[0][nt] = wlane[nt * 32];

    #pragma unroll
    for (int kp = 0; kp < 8; kp++) {
        if (kp < 7) {
            #pragma unroll
            for (int nt = 0; nt < 4; nt++)
                b[(kp + 1) & 1][nt] = wlane[(kp + 1) * 1024 + nt * 32];
        }
        uint32_t a[2][4];
        ldmA(a[0], a0 + (2 * kp) * 32);
        ldmA(a[1], a0 + (2 * kp) * 32 + 16 * LDH * 2);
        #pragma unroll
        for (int mt = 0; mt < 2; mt++)
            #pragma unroll
            for (int nt = 0; nt < 4; nt++)
                mma16816(acc[mt][nt], a[mt], b[kp & 1][nt].x, b[kp & 1][nt].y);
        ldmA(a[0], a0 + (2 * kp + 1) * 32);
        ldmA(a[1], a0 + (2 * kp + 1) * 32 + 16 * LDH * 2);
        #pragma unroll
        for (int mt = 0; mt < 2; mt++)
            #pragma unroll
            for (int nt = 0; nt < 4; nt++)
                mma16816(acc[mt][nt], a[mt], b[kp & 1][nt].z, b[kp & 1][nt].w);
    }
}

// SMEM layout (bytes) -- ~84.5KB/CTA -> 2 CTAs per SM
#define SM_E   0
#define SM_H   (MT * LDE * 2)                 // 16896
#define SM_O   (SM_H + MT * LDH * 2)          // 50176
#define SM_LJ  (SM_O + MT * LDO * 4)          // 83456
#define SM_TOT (SM_LJ + MT * 8 * 4)           // 84480

__global__ void __launch_bounds__(THREADS, 2) nvp_main(
    const float* __restrict__ z,
    const float* __restrict__ bs1, const float* __restrict__ bs2,
    const float* __restrict__ bt1, const float* __restrict__ bt2,
    float* __restrict__ out)
{
    extern __shared__ char smraw[];
    __half* e_s  = reinterpret_cast<__half*>(smraw + SM_E);
    __half* h_s  = reinterpret_cast<__half*>(smraw + SM_H);
    float*  o_s  = reinterpret_cast<float*>(smraw + SM_O);
    float*  lj_s = reinterpret_cast<float*>(smraw + SM_LJ);

    const int tid  = threadIdx.x;
    const int row0 = blockIdx.x * MT;

    // Load: z row -> (e f16 smem, o f32 smem); even half of output is the identity copy.
    for (int idx = tid; idx < MT * 256; idx += THREADS) {
        int r = idx >> 8, c = idx & 255;
        float2 p = reinterpret_cast<const float2*>(z + (size_t)(row0 + r) * DD)[c];
        e_s[r * LDE + c] = __float2half_rn(p.x);
        o_s[r * LDO + c] = p.y;
        out[(size_t)(row0 + r) * DD + c] = p.x;
    }
    __syncthreads();

    const int warp = tid >> 5, lane = tid & 31;
    const int wn = warp;                          // 8 warps along N
    const int g = lane >> 2, tg = lane & 3;
    const int mat = lane >> 3, within = lane & 7;
    const int rowoff = ((mat & 1) << 3) + within; // ldmatrix per-lane row
    const int koff   = (mat >> 1) << 3;
    const uint32_t aE = (uint32_t)__cvta_generic_to_shared(e_s);
    const uint32_t aH = (uint32_t)__cvta_generic_to_shared(h_s);

    // G1 (fused) per-warp selections: warps 0-3 -> Ws1/bs1, warps 4-7 -> Wt1/bt1
    const int g1mat  = (wn >= 4) ? 2 : 0;
    const int g1nt0  = (wn & 3) * 8;              // first ntile of this warp's 64-col slice
    const float* g1bias = (wn >= 4) ? bt1 : bs1;  // + layer*256 + (wn&3)*64 later

    float lj[4] = {0.f, 0.f, 0.f, 0.f};
    float acc[2][8][4];

    for (int layer = 0; layer < NL; layer++) {
        const uint4* wbase = g_wpack + (size_t)(layer * 4) * 8192;

        // ---------- G1 (fused): h[:, wn*64..] = relu(e @ [Ws1|Wt1] + [bs1|bt1]) ----------
        gemm512(aE, wbase + (size_t)g1mat * 8192 + g1nt0 * 32 + lane,
                acc, rowoff, koff);
        __syncthreads();   // all warps done reading h (prev layer G2t)
        {
            const float* bb_base = g1bias + layer * 256 + (wn & 3) * 64;
            #pragma unroll
            for (int mt = 0; mt < 2; mt++)
                #pragma unroll
                for (int j = 0; j < 8; j++) {
                    int cloc = j * 8 + tg * 2;            // within 64-col slice
                    float2 bb = *reinterpret_cast<const float2*>(bb_base + cloc);
                    int hcol = wn * 64 + cloc;
                    int r0 = mt * 16 + g;
                    __half2 v0 = __floats2half2_rn(fmaxf(acc[mt][j][0] + bb.x, 0.f),
                                                   fmaxf(acc[mt][j][1] + bb.y, 0.f));
                    __half2 v1 = __floats2half2_rn(fmaxf(acc[mt][j][2] + bb.x, 0.f),
                                                   fmaxf(acc[mt][j][3] + bb.y, 0.f));
                    *reinterpret_cast<__half2*>(h_s + r0 * LDH + hcol)       = v0;
                    *reinterpret_cast<__half2*>(h_s + (r0 + 8) * LDH + hcol) = v1;
                }
        }
        __syncthreads();

        // ---------- G2s: s = tanh(h_s @ Ws2 + bs2) ; o *= exp(s) ; lj += s ----------
        gemm256(aH, 0, wbase + (size_t)1 * 8192 + (wn * 4) * 32 + lane,
                acc, rowoff, koff);
        #pragma unroll
        for (int mt = 0; mt < 2; mt++)
            #pragma unroll
            for (int nt = 0; nt < 4; nt++) {
                int col0 = wn * 32 + nt * 8 + tg * 2;
                float2 bb = *reinterpret_cast<const float2*>(bs2 + layer * HALFD + col0);
                int r0 = mt * 16 + g;
                float s0 = tanh_acc(acc[mt][nt][0] + bb.x);
                float s1 = tanh_acc(acc[mt][nt][1] + bb.y);
                float s2 = tanh_acc(acc[mt][nt][2] + bb.x);
                float s3 = tanh_acc(acc[mt][nt][3] + bb.y);
                lj[mt * 2]     += s0 + s1;
                lj[mt * 2 + 1] += s2 + s3;
                float2 oa = *reinterpret_cast<float2*>(o_s + r0 * LDO + col0);
                float2 ob = *reinterpret_cast<float2*>(o_s + (r0 + 8) * LDO + col0);
                oa.x *= __expf(s0);  oa.y *= __expf(s1);
                ob.x *= __expf(s2);  ob.y *= __expf(s3);
                *reinterpret_cast<float2*>(o_s + r0 * LDO + col0)       = oa;
                *reinterpret_cast<float2*>(o_s + (r0 + 8) * LDO + col0) = ob;
            }

        // ---------- G2t: t = h_t @ Wt2 + bt2 ; o += t ----------
        gemm256(aH, 256, wbase + (size_t)3 * 8192 + (wn * 4) * 32 + lane,
                acc, rowoff, koff);
        #pragma unroll
        for (int mt = 0; mt < 2; mt++)
            #pragma unroll
            for (int nt = 0; nt < 4; nt++) {
                int col0 = wn * 32 + nt * 8 + tg * 2;
                float2 bb = *reinterpret_cast<const float2*>(bt2 + layer * HALFD + col0);
                int r0 = mt * 16 + g;
                float2 oa = *reinterpret_cast<float2*>(o_s + r0 * LDO + col0);
                float2 ob = *reinterpret_cast<float2*>(o_s + (r0 + 8) * LDO + col0);
                oa.x += acc[mt][nt][0] + bb.x;
                oa.y += acc[mt][nt][1] + bb.y;
                ob.x += acc[mt][nt][2] + bb.x;
                ob.y += acc[mt][nt][3] + bb.y;
                *reinterpret_cast<float2*>(o_s + r0 * LDO + col0)       = oa;
                *reinterpret_cast<float2*>(o_s + (r0 + 8) * LDO + col0) = ob;
            }
        // o is thread-private; h protected by the two syncs around its rewrite
    }
    __syncthreads();

    // Odd half of output
    for (int idx = tid; idx < MT * 256; idx += THREADS) {
        int r = idx >> 8, c = idx & 255;
        out[(size_t)(row0 + r) * DD + 256 + c] = o_s[r * LDO + c];
    }

    // Deterministic logjac reduction: intra-warp over tg, then across the 8 n-warps.
    #pragma unroll
    for (int k = 0; k < 4; k++) {
        float v = lj[k];
        v += __shfl_down_sync(0xffffffffu, v, 2);
        v += __shfl_down_sync(0xffffffffu, v, 1);
        if (tg == 0) {
            int r = (k >> 1) * 16 + (k & 1) * 8 + g;
            lj_s[r * 8 + wn] = v;
        }
    }
    __syncthreads();
    if (tid < MT) {
        float v = 0.f;
        #pragma unroll
        for (int j = 0; j < 8; j++) v += lj_s[tid * 8 + j];
        out[(size_t)NROWS * DD + row0 + tid] = v;
    }
}

extern "C" void kernel_launch(void* const* d_in, const int* in_sizes, int n_in,
                              void* d_out, int out_size)
{
    const float* z   = (const float*)d_in[0];
    const float* Ws1 = (const float*)d_in[1];
    const float* bs1 = (const float*)d_in[2];
    const float* Ws2 = (const float*)d_in[3];
    const float* bs2 = (const float*)d_in[4];
    const float* Wt1 = (const float*)d_in[5];
    const float* bt1 = (const float*)d_in[6];
    const float* Wt2 = (const float*)d_in[7];
    const float* bt2 = (const float*)d_in[8];
    float* out = (float*)d_out;

    static bool attr_set = false;
    if (!attr_set) {
        cudaFuncSetAttribute(nvp_main, cudaFuncAttributeMaxDynamicSharedMemorySize, SM_TOT);
        attr_set = true;
    }

    // 1) pack weights: kpair-fused fragment layout (LDG.128)
    pack_w<<<(NL * 4 * 8 * 32 * 32 + 255) / 256, 256>>>(Ws1, Ws2, Wt1, Wt2);

    // 2) fused 8-layer RealNVP: fused G1 (N=512), in-place o-update, 2 syncs/layer, 2 CTAs/SM
    nvp_main<<<NCTAS, THREADS, SM_TOT>>>(z, bs1, bs2, bt1, bt2, out);
}